// round 12
// baseline (speedup 1.0000x reference)
#include <cuda_runtime.h>
#include <cuda_fp16.h>
#include <cstdint>

// ---------------- problem constants ----------------
#define NB      16
#define INC     64
#define OUTC    64
#define HW      128
#define OW      126
#define FC      512
#define GROUPS  4
#define OPG     9232
#define IPG     128
#define CNNP    36928
#define NWCOL   36864

// ---------------- scratch (device-code refs only) ----------------
__device__ float g_h1[NB * FC];
__device__ float g_h2[NB * FC];
// pre-split, pre-swizzled weights: [b][ky][kx][part][oc][ic(swizzled units)]
__device__ __half g_wm[NB][3][3][2][64][64];
__device__ float g_bias[NB * OUTC];

// smem layout (dynamic)
#define WIMG      49152      // one ky weight image
#define SM_W      0          // 2 x WIMG (double buffer)
#define SM_X      98304      // 2 x XBUF2 (double buffer, 2 rows each)
#define XBUF2     65536      // two x rows
#define XROW      32768      // one x row (2 parts x 16384)
#define XPART     16384
#define SM_BIAS   229376     // 256 B
#define SM_TOTAL  229632

#define PAIRS_PER_CTA 7      // 7 pairs = 14 rows
#define CTA_PER_B     9      // 9 * 14 = 126 rows
#define NSTAGE        (PAIRS_PER_CTA * 3)   // 21

// named barriers: FULL = 1+buf, EMPTY = 3+buf, 512 threads each
#define BAR_SYNC(id)   asm volatile("bar.sync %0, 512;"   :: "r"(id) : "memory")
#define BAR_ARRIVE(id) asm volatile("bar.arrive %0, 512;" :: "r"(id) : "memory")

// ---------------- PTX helpers ----------------
__device__ __forceinline__ unsigned int smem_u32(const void* p) {
    unsigned int a;
    asm("{ .reg .u64 t; cvta.to.shared.u64 t, %1; cvt.u32.u64 %0, t; }"
        : "=r"(a) : "l"(p));
    return a;
}
__device__ __forceinline__ void cp_async16(unsigned int sdst, const void* gsrc) {
    asm volatile("cp.async.cg.shared.global [%0], [%1], 16;" :: "r"(sdst), "l"(gsrc));
}
__device__ __forceinline__ void cp_commit() { asm volatile("cp.async.commit_group;"); }
__device__ __forceinline__ void cp_wait0()  { asm volatile("cp.async.wait_group 0;"); }

__device__ __forceinline__ void ldsm_x4(uint32_t& r0, uint32_t& r1, uint32_t& r2,
                                        uint32_t& r3, uint32_t addr) {
    asm volatile("ldmatrix.sync.aligned.m8n8.x4.shared.b16 {%0,%1,%2,%3}, [%4];"
                 : "=r"(r0), "=r"(r1), "=r"(r2), "=r"(r3) : "r"(addr));
}
__device__ __forceinline__ void mma16816(float* c, const uint32_t* a,
                                         uint32_t b0, uint32_t b1) {
    asm volatile(
        "mma.sync.aligned.m16n8k16.row.col.f32.f16.f16.f32 "
        "{%0,%1,%2,%3}, {%4,%5,%6,%7}, {%8,%9}, {%0,%1,%2,%3};"
        : "+f"(c[0]), "+f"(c[1]), "+f"(c[2]), "+f"(c[3])
        : "r"(a[0]), "r"(a[1]), "r"(a[2]), "r"(a[3]), "r"(b0), "r"(b1));
}
__device__ __forceinline__ uint32_t pack_h2(__half a, __half b) {
    return (uint32_t)__half_as_ushort(a) | ((uint32_t)__half_as_ushort(b) << 16);
}

// ============================================================
// Kernel 1: GEMV + bias + relu, warp-per-output.
// ============================================================
__device__ __forceinline__ void gemv_body(
    const float* __restrict__ in, const float* __restrict__ W,
    const float* __restrict__ bias, float* __restrict__ out)
{
    const int lane = threadIdx.x & 31;
    const int warp = threadIdx.x >> 5;
    const int b = blockIdx.y;
    const int t = blockIdx.x * 8 + warp;

    const float4* in4 = reinterpret_cast<const float4*>(in + (size_t)b * FC);
    const float4* w4  = reinterpret_cast<const float4*>(W + (size_t)t * FC);

    float s = 0.f;
    #pragma unroll
    for (int i = 0; i < 4; i++) {
        float4 a = in4[lane + 32 * i];
        float4 w = w4[lane + 32 * i];
        s += a.x * w.x + a.y * w.y + a.z * w.z + a.w * w.w;
    }
    #pragma unroll
    for (int off = 16; off > 0; off >>= 1)
        s += __shfl_xor_sync(0xffffffffu, s, off);
    if (lane == 0)
        out[(size_t)b * FC + t] = fmaxf(s + bias[t], 0.f);
}
__global__ __launch_bounds__(256) void gemv1_kernel(
    const float* __restrict__ fc_in, const float* __restrict__ w1,
    const float* __restrict__ b1) { gemv_body(fc_in, w1, b1, g_h1); }
__global__ __launch_bounds__(256) void gemv2_kernel(
    const float* __restrict__ w2, const float* __restrict__ b2) { gemv_body(g_h1, w2, b2, g_h2); }

// ============================================================
// Kernel 2: wbgen -> hi/lo-split, unit-swizzled weight images + bias.
// ============================================================
__global__ __launch_bounds__(256) void wbgen_kernel(
    const float* __restrict__ w3, const float* __restrict__ b3)
{
    __shared__ __align__(16) float4 s_h2[NB][IPG / 4];
    int g = blockIdx.x;
    int j = blockIdx.y * 256 + threadIdx.x;

    for (int e = threadIdx.x; e < NB * IPG / 4; e += 256) {
        int bb = e >> 5, k = e & 31;
        s_h2[bb][k] = reinterpret_cast<const float4*>(g_h2 + bb * FC + g * IPG)[k];
    }
    __syncthreads();
    if (j >= OPG) return;

    float acc[NB];
    #pragma unroll
    for (int bb = 0; bb < NB; bb++) acc[bb] = 0.f;

    const float4* wr = reinterpret_cast<const float4*>(w3 + ((size_t)g * OPG + j) * IPG);
    #pragma unroll 4
    for (int k = 0; k < IPG / 4; k++) {
        float4 w = wr[k];
        #pragma unroll
        for (int bb = 0; bb < NB; bb++) {
            float4 h = s_h2[bb][k];
            acc[bb] += w.x * h.x + w.y * h.y + w.z * h.z + w.w * h.w;
        }
    }
    float bias = b3[g * OPG + j];
    int col = g * OPG + j;

    if (col < NWCOL) {
        // col = oc*576 + ic*9 + ky*3 + kx
        int oc = col / 576;
        int r  = col - oc * 576;
        int ic = r / 9;
        int kt = r - ic * 9;
        int ky = kt / 3;
        int kx = kt - ky * 3;
        int ic_sw = (((ic >> 3) ^ (oc & 7)) << 3) | (ic & 7);
        #pragma unroll
        for (int bb = 0; bb < NB; bb++) {
            float w = fmaxf(acc[bb] + bias, 0.f);
            __half hi = __float2half_rn(w);
            __half lo = __float2half_rn(w - __half2float(hi));
            g_wm[bb][ky][kx][0][oc][ic_sw] = hi;
            g_wm[bb][ky][kx][1][oc][ic_sw] = lo;
        }
    } else {
        int oc = col - NWCOL;
        #pragma unroll
        for (int bb = 0; bb < NB; bb++)
            g_bias[bb * OUTC + oc] = fmaxf(acc[bb] + bias, 0.f);
    }
}

// ============================================================
// Kernel 3: warp-specialized HMMA conv, TWO output rows per stage.
// 512 threads: warps 0-7 consumers, 8-15 producers.
// CTA = 14 rows (7 pairs) of one sample; stage = (pair, ky).
// A (weight) fragments loaded once per ks and reused for both rows:
// 12 LDSM : 48 HMMA (was 16 : 48) -> smem crossbar relieved.
// ============================================================
__global__ __launch_bounds__(512, 1) void conv_mma(
    const float* __restrict__ x, float* __restrict__ out)
{
    extern __shared__ char smem[];
    const uint32_t sb = smem_u32(smem);
    const int tid  = threadIdx.x;
    const int warp = tid >> 5;
    const int L    = tid & 31;

    const int b   = blockIdx.x / CTA_PER_B;
    const int oy0 = (blockIdx.x - b * CTA_PER_B) * (2 * PAIRS_PER_CTA);

    float* s_bias = reinterpret_cast<float*>(smem + SM_BIAS);
    if (tid < OUTC) s_bias[tid] = g_bias[b * OUTC + tid];

    if (warp < 8) {
        // ======================= CONSUMERS =======================
        const int gq  = L >> 3;
        const int gi  = L & 7;
        const int ocw = (warp & 1) * 32;
        const int pxw = (warp >> 1) * 32;

        float acc[2][2][4][4];   // [row][mt][nt][4]
        #pragma unroll
        for (int r = 0; r < 2; r++)
            #pragma unroll
            for (int mt = 0; mt < 2; mt++)
                #pragma unroll
                for (int nt = 0; nt < 4; nt++)
                    #pragma unroll
                    for (int i = 0; i < 4; i++) acc[r][mt][nt][i] = 0.f;

        for (int s = 0; s < NSTAGE; s++) {
            const int buf = s & 1;
            BAR_SYNC(1 + buf);                       // wait FULL

            const uint32_t wb_ = sb + SM_W + (uint32_t)buf * WIMG;
            const uint32_t xb_ = sb + SM_X + (uint32_t)buf * XBUF2;

            for (int kx = 0; kx < 3; kx++) {
                #pragma unroll
                for (int ks = 0; ks < 4; ks++) {
                    const int ub = ks * 2;
                    // A fragments (weights): loaded ONCE, reused for 2 rows
                    uint32_t a[2][2][4];
                    #pragma unroll
                    for (int mt = 0; mt < 2; mt++) {
                        #pragma unroll
                        for (int part = 0; part < 2; part++) {
                            int row = ocw + mt * 16 + (gq & 1) * 8 + gi;
                            int u   = ub + (gq >> 1);
                            uint32_t addr = wb_ +
                                (uint32_t)(((kx * 2 + part) * 64 + row) * 128 +
                                           ((u ^ (row & 7)) * 16));
                            ldsm_x4(a[mt][part][0], a[mt][part][1],
                                    a[mt][part][2], a[mt][part][3], addr);
                        }
                    }
                    #pragma unroll
                    for (int r = 0; r < 2; r++) {
                        uint32_t bb[2][2][4];
                        #pragma unroll
                        for (int part = 0; part < 2; part++) {
                            #pragma unroll
                            for (int np = 0; np < 2; np++) {
                                int c = pxw + np * 16 + kx + (gq >> 1) * 8 + gi;
                                if (c > 127) c = 127;   // feeds only discarded px
                                uint32_t addr = xb_ + (uint32_t)r * XROW +
                                    (uint32_t)part * XPART +
                                    (uint32_t)(c * 128 +
                                               (((ub + (gq & 1)) ^ (c & 7)) * 16));
                                ldsm_x4(bb[part][np][0], bb[part][np][1],
                                        bb[part][np][2], bb[part][np][3], addr);
                            }
                        }
                        #pragma unroll
                        for (int mt = 0; mt < 2; mt++) {
                            #pragma unroll
                            for (int nt = 0; nt < 4; nt++) {
                                int np = nt >> 1, q2 = (nt & 1) * 2;
                                mma16816(acc[r][mt][nt], a[mt][0],
                                         bb[0][np][q2], bb[0][np][q2 + 1]);
                                mma16816(acc[r][mt][nt], a[mt][0],
                                         bb[1][np][q2], bb[1][np][q2 + 1]);
                                mma16816(acc[r][mt][nt], a[mt][1],
                                         bb[0][np][q2], bb[0][np][q2 + 1]);
                            }
                        }
                    }
                }
            }

            BAR_ARRIVE(3 + buf);                     // signal EMPTY

            // ---- epilogue at pair end: both rows ----
            if (s % 3 == 2) {
                const int oyp = oy0 + (s / 3) * 2;
                const int r4 = L >> 2;
                const int q  = (L & 3) * 2;
                #pragma unroll
                for (int r = 0; r < 2; r++) {
                    const int oy = oyp + r;
                    #pragma unroll
                    for (int mt = 0; mt < 2; mt++) {
                        int oc = ocw + mt * 16 + r4;
                        float bi0 = s_bias[oc];
                        float bi1 = s_bias[oc + 8];
                        #pragma unroll
                        for (int nt = 0; nt < 4; nt++) {
                            int px = pxw + nt * 8 + q;
                            if (px < OW) {
                                float* o = out + (((size_t)(b * OUTC + oc)) * OW + oy) * OW + px;
                                float2 v0 = make_float2(acc[r][mt][nt][0] + bi0,
                                                        acc[r][mt][nt][1] + bi0);
                                float2 v1 = make_float2(acc[r][mt][nt][2] + bi1,
                                                        acc[r][mt][nt][3] + bi1);
                                *reinterpret_cast<float2*>(o) = v0;
                                *reinterpret_cast<float2*>(o + (size_t)8 * OW * OW) = v1;
                            }
                            #pragma unroll
                            for (int i = 0; i < 4; i++) acc[r][mt][nt][i] = 0.f;
                        }
                    }
                }
            }
        }
    } else {
        // ======================= PRODUCERS =======================
        const int pw   = warp - 8;       // 0..7
        const int ptid = tid - 256;      // 0..255
        const int ic0  = pw * 8;

        for (int s = 0; s < NSTAGE; s++) {
            const int buf  = s & 1;
            const int pair = s / 3;
            const int ky   = s - 3 * pair;

            if (s >= 2) BAR_SYNC(3 + buf);           // wait EMPTY

            // ---- W image for (b, ky): flat cp.async (48 KB) ----
            {
                const char* src = reinterpret_cast<const char*>(&g_wm[b][ky][0][0][0][0]);
                const uint32_t dst = sb + SM_W + (uint32_t)buf * WIMG;
                #pragma unroll
                for (int i = 0; i < 12; i++) {
                    uint32_t e = ((uint32_t)ptid + (uint32_t)i * 256u) * 16u;
                    cp_async16(dst + e, src + e);
                }
                cp_commit();
            }

            // ---- two x rows: y = oy0 + pair*2 + r + ky ----
            #pragma unroll
            for (int r = 0; r < 2; r++) {
                const int y = oy0 + pair * 2 + r + ky;   // <= 127
                const float* xr = x + ((size_t)b * INC * HW + (size_t)y) * HW;
                const uint32_t xbase = SM_X + (uint32_t)buf * XBUF2 + (uint32_t)r * XROW;
                #pragma unroll
                for (int k = 0; k < 4; k++) {
                    int c = k * 32 + L;              // 0..127
                    float v[8];
                    #pragma unroll
                    for (int i = 0; i < 8; i++)
                        v[i] = __ldg(xr + (size_t)(ic0 + i) * HW * HW + c);
                    uint32_t hi[4], lo[4];
                    #pragma unroll
                    for (int i = 0; i < 4; i++) {
                        __half h0 = __float2half_rn(v[2 * i]);
                        __half h1 = __float2half_rn(v[2 * i + 1]);
                        __half l0 = __float2half_rn(v[2 * i]     - __half2float(h0));
                        __half l1 = __float2half_rn(v[2 * i + 1] - __half2float(h1));
                        hi[i] = pack_h2(h0, h1);
                        lo[i] = pack_h2(l0, l1);
                    }
                    uint32_t p   = (uint32_t)(pw ^ (c & 7));
                    uint32_t off = xbase + (uint32_t)c * 128u + p * 16u;
                    *reinterpret_cast<uint4*>(smem + off) =
                        make_uint4(hi[0], hi[1], hi[2], hi[3]);
                    *reinterpret_cast<uint4*>(smem + off + XPART) =
                        make_uint4(lo[0], lo[1], lo[2], lo[3]);
                }
            }

            cp_wait0();                              // W copies landed
            BAR_ARRIVE(1 + buf);                     // signal FULL
        }
    }
}

// ============================================================
extern "C" void kernel_launch(void* const* d_in, const int* in_sizes, int n_in,
                              void* d_out, int out_size)
{
    const float* x     = (const float*)d_in[0];
    const float* fc_in = (const float*)d_in[1];
    const float* w1    = (const float*)d_in[2];
    const float* b1    = (const float*)d_in[3];
    const float* w2    = (const float*)d_in[4];
    const float* b2    = (const float*)d_in[5];
    const float* w3    = (const float*)d_in[6];
    const float* b3    = (const float*)d_in[7];
    float* out = (float*)d_out;

    cudaFuncSetAttribute(conv_mma, cudaFuncAttributeMaxDynamicSharedMemorySize, SM_TOTAL);

    gemv1_kernel<<<dim3(FC / 8, NB), 256>>>(fc_in, w1, b1);
    gemv2_kernel<<<dim3(FC / 8, NB), 256>>>(w2, b2);
    wbgen_kernel<<<dim3(GROUPS, (OPG + 255) / 256), 256>>>(w3, b3);
    conv_mma<<<NB * CTA_PER_B, 512, SM_TOTAL>>>(x, out);
}

// round 13
// speedup vs baseline: 1.3639x; 1.3639x over previous
#include <cuda_runtime.h>
#include <cuda_fp16.h>
#include <cstdint>

// ---------------- problem constants ----------------
#define NB      16
#define INC     64
#define OUTC    64
#define HW      128
#define OW      126
#define FC      512
#define GROUPS  4
#define OPG     9232
#define IPG     128
#define CNNP    36928
#define NWCOL   36864

// ---------------- scratch (device-code refs only) ----------------
__device__ float g_h1[NB * FC];
__device__ float g_h2[NB * FC];
// single-fp16 weights, pre-swizzled: [b][ky][kx][oc][ic(swizzled units)]
__device__ __half g_wm[NB][3][3][64][64];
__device__ float g_bias[NB * OUTC];

// smem layout (dynamic)
#define WIMG      24576      // one ky weight image (3 kx x 64 oc x 128 B)
#define SM_W      0          // 2 x WIMG (double buffer)
#define SM_X      49152      // 2 x 32768 (double buffer)
#define XBUF      32768
#define XPART     16384
#define SM_BIAS   114688     // 256 B
#define SM_TOTAL  114944

#define TILES_PER_CTA 7
#define CTA_PER_B     18     // 18 * 7 = 126 rows
#define NSTAGE        (TILES_PER_CTA * 3)   // 21

// named barriers: FULL = 1+buf, EMPTY = 3+buf, 512 threads each
#define BAR_SYNC(id)   asm volatile("bar.sync %0, 512;"   :: "r"(id) : "memory")
#define BAR_ARRIVE(id) asm volatile("bar.arrive %0, 512;" :: "r"(id) : "memory")

// ---------------- PTX helpers ----------------
__device__ __forceinline__ unsigned int smem_u32(const void* p) {
    unsigned int a;
    asm("{ .reg .u64 t; cvta.to.shared.u64 t, %1; cvt.u32.u64 %0, t; }"
        : "=r"(a) : "l"(p));
    return a;
}
__device__ __forceinline__ void cp_async16(unsigned int sdst, const void* gsrc) {
    asm volatile("cp.async.cg.shared.global [%0], [%1], 16;" :: "r"(sdst), "l"(gsrc));
}
__device__ __forceinline__ void cp_commit() { asm volatile("cp.async.commit_group;"); }
__device__ __forceinline__ void cp_wait0()  { asm volatile("cp.async.wait_group 0;"); }

__device__ __forceinline__ void ldsm_x4(uint32_t& r0, uint32_t& r1, uint32_t& r2,
                                        uint32_t& r3, uint32_t addr) {
    asm volatile("ldmatrix.sync.aligned.m8n8.x4.shared.b16 {%0,%1,%2,%3}, [%4];"
                 : "=r"(r0), "=r"(r1), "=r"(r2), "=r"(r3) : "r"(addr));
}
__device__ __forceinline__ void mma16816(float* c, const uint32_t* a,
                                         uint32_t b0, uint32_t b1) {
    asm volatile(
        "mma.sync.aligned.m16n8k16.row.col.f32.f16.f16.f32 "
        "{%0,%1,%2,%3}, {%4,%5,%6,%7}, {%8,%9}, {%0,%1,%2,%3};"
        : "+f"(c[0]), "+f"(c[1]), "+f"(c[2]), "+f"(c[3])
        : "r"(a[0]), "r"(a[1]), "r"(a[2]), "r"(a[3]), "r"(b0), "r"(b1));
}
__device__ __forceinline__ uint32_t pack_h2(__half a, __half b) {
    return (uint32_t)__half_as_ushort(a) | ((uint32_t)__half_as_ushort(b) << 16);
}

// ============================================================
// Kernel 1: GEMV + bias + relu, warp-per-output.
// ============================================================
__device__ __forceinline__ void gemv_body(
    const float* __restrict__ in, const float* __restrict__ W,
    const float* __restrict__ bias, float* __restrict__ out)
{
    const int lane = threadIdx.x & 31;
    const int warp = threadIdx.x >> 5;
    const int b = blockIdx.y;
    const int t = blockIdx.x * 8 + warp;

    const float4* in4 = reinterpret_cast<const float4*>(in + (size_t)b * FC);
    const float4* w4  = reinterpret_cast<const float4*>(W + (size_t)t * FC);

    float s = 0.f;
    #pragma unroll
    for (int i = 0; i < 4; i++) {
        float4 a = in4[lane + 32 * i];
        float4 w = w4[lane + 32 * i];
        s += a.x * w.x + a.y * w.y + a.z * w.z + a.w * w.w;
    }
    #pragma unroll
    for (int off = 16; off > 0; off >>= 1)
        s += __shfl_xor_sync(0xffffffffu, s, off);
    if (lane == 0)
        out[(size_t)b * FC + t] = fmaxf(s + bias[t], 0.f);
}
__global__ __launch_bounds__(256) void gemv1_kernel(
    const float* __restrict__ fc_in, const float* __restrict__ w1,
    const float* __restrict__ b1) { gemv_body(fc_in, w1, b1, g_h1); }
__global__ __launch_bounds__(256) void gemv2_kernel(
    const float* __restrict__ w2, const float* __restrict__ b2) { gemv_body(g_h1, w2, b2, g_h2); }

// ============================================================
// Kernel 2: wbgen -> single-fp16, unit-swizzled weight images + bias.
// ============================================================
__global__ __launch_bounds__(256) void wbgen_kernel(
    const float* __restrict__ w3, const float* __restrict__ b3)
{
    __shared__ __align__(16) float4 s_h2[NB][IPG / 4];
    int g = blockIdx.x;
    int j = blockIdx.y * 256 + threadIdx.x;

    for (int e = threadIdx.x; e < NB * IPG / 4; e += 256) {
        int bb = e >> 5, k = e & 31;
        s_h2[bb][k] = reinterpret_cast<const float4*>(g_h2 + bb * FC + g * IPG)[k];
    }
    __syncthreads();
    if (j >= OPG) return;

    float acc[NB];
    #pragma unroll
    for (int bb = 0; bb < NB; bb++) acc[bb] = 0.f;

    const float4* wr = reinterpret_cast<const float4*>(w3 + ((size_t)g * OPG + j) * IPG);
    #pragma unroll 4
    for (int k = 0; k < IPG / 4; k++) {
        float4 w = wr[k];
        #pragma unroll
        for (int bb = 0; bb < NB; bb++) {
            float4 h = s_h2[bb][k];
            acc[bb] += w.x * h.x + w.y * h.y + w.z * h.z + w.w * h.w;
        }
    }
    float bias = b3[g * OPG + j];
    int col = g * OPG + j;

    if (col < NWCOL) {
        // col = oc*576 + ic*9 + ky*3 + kx
        int oc = col / 576;
        int r  = col - oc * 576;
        int ic = r / 9;
        int kt = r - ic * 9;
        int ky = kt / 3;
        int kx = kt - ky * 3;
        int ic_sw = (((ic >> 3) ^ (oc & 7)) << 3) | (ic & 7);
        #pragma unroll
        for (int bb = 0; bb < NB; bb++) {
            float w = fmaxf(acc[bb] + bias, 0.f);
            g_wm[bb][ky][kx][oc][ic_sw] = __float2half_rn(w);
        }
    } else {
        int oc = col - NWCOL;
        #pragma unroll
        for (int bb = 0; bb < NB; bb++)
            g_bias[bb * OUTC + oc] = fmaxf(acc[bb] + bias, 0.f);
    }
}

// ============================================================
// Kernel 3: warp-specialized HMMA implicit-GEMM conv, 2-MMA split.
// W single fp16 (rounding error carried by x_hi*w only), x hi/lo split:
// D += x_hi*w + x_lo*w  (exact fp16 products, fp32 accum).
// 512 threads: warps 0-7 consumers, 8-15 producers; stage=(tile,ky),
// double-buffered W image + x row, named-barrier pipeline.
// ============================================================
__global__ __launch_bounds__(512, 1) void conv_mma(
    const float* __restrict__ x, float* __restrict__ out)
{
    extern __shared__ char smem[];
    const uint32_t sb = smem_u32(smem);
    const int tid  = threadIdx.x;
    const int warp = tid >> 5;
    const int L    = tid & 31;

    const int b   = blockIdx.x / CTA_PER_B;
    const int oy0 = (blockIdx.x - b * CTA_PER_B) * TILES_PER_CTA;

    float* s_bias = reinterpret_cast<float*>(smem + SM_BIAS);
    if (tid < OUTC) s_bias[tid] = g_bias[b * OUTC + tid];

    if (warp < 8) {
        // ======================= CONSUMERS =======================
        const int gq  = L >> 3;
        const int gi  = L & 7;
        const int ocw = (warp & 1) * 32;
        const int pxw = (warp >> 1) * 32;

        float acc[2][4][4];
        #pragma unroll
        for (int mt = 0; mt < 2; mt++)
            #pragma unroll
            for (int nt = 0; nt < 4; nt++)
                #pragma unroll
                for (int i = 0; i < 4; i++) acc[mt][nt][i] = 0.f;

        for (int s = 0; s < NSTAGE; s++) {
            const int buf = s & 1;
            BAR_SYNC(1 + buf);                       // wait FULL

            const uint32_t wb_ = sb + SM_W + (uint32_t)buf * WIMG;
            const uint32_t xb_ = sb + SM_X + (uint32_t)buf * XBUF;

            for (int kx = 0; kx < 3; kx++) {
                #pragma unroll
                for (int ks = 0; ks < 4; ks++) {
                    const int ub = ks * 2;
                    // A fragments (weights, single part)
                    uint32_t a[2][4];
                    #pragma unroll
                    for (int mt = 0; mt < 2; mt++) {
                        int row = ocw + mt * 16 + (gq & 1) * 8 + gi;
                        int u   = ub + (gq >> 1);
                        uint32_t addr = wb_ +
                            (uint32_t)((kx * 64 + row) * 128 +
                                       ((u ^ (row & 7)) * 16));
                        ldsm_x4(a[mt][0], a[mt][1], a[mt][2], a[mt][3], addr);
                    }
                    // B fragments (x hi + lo parts)
                    uint32_t bb[2][2][4];
                    #pragma unroll
                    for (int part = 0; part < 2; part++) {
                        #pragma unroll
                        for (int np = 0; np < 2; np++) {
                            int c = pxw + np * 16 + kx + (gq >> 1) * 8 + gi;
                            if (c > 127) c = 127;    // feeds only discarded px
                            uint32_t addr = xb_ + (uint32_t)part * XPART +
                                (uint32_t)(c * 128 + (((ub + (gq & 1)) ^ (c & 7)) * 16));
                            ldsm_x4(bb[part][np][0], bb[part][np][1],
                                    bb[part][np][2], bb[part][np][3], addr);
                        }
                    }
                    #pragma unroll
                    for (int mt = 0; mt < 2; mt++) {
                        #pragma unroll
                        for (int nt = 0; nt < 4; nt++) {
                            int np = nt >> 1, q2 = (nt & 1) * 2;
                            mma16816(acc[mt][nt], a[mt], bb[0][np][q2], bb[0][np][q2 + 1]);
                            mma16816(acc[mt][nt], a[mt], bb[1][np][q2], bb[1][np][q2 + 1]);
                        }
                    }
                }
            }

            BAR_ARRIVE(3 + buf);                     // signal EMPTY

            // ---- epilogue at tile end ----
            if (s % 3 == 2) {
                const int oy = oy0 + s / 3;
                const int r4 = L >> 2;
                const int q  = (L & 3) * 2;
                #pragma unroll
                for (int mt = 0; mt < 2; mt++) {
                    int oc = ocw + mt * 16 + r4;
                    float bi0 = s_bias[oc];
                    float bi1 = s_bias[oc + 8];
                    #pragma unroll
                    for (int nt = 0; nt < 4; nt++) {
                        int px = pxw + nt * 8 + q;
                        if (px < OW) {
                            float* o = out + (((size_t)(b * OUTC + oc)) * OW + oy) * OW + px;
                            float2 v0 = make_float2(acc[mt][nt][0] + bi0, acc[mt][nt][1] + bi0);
                            float2 v1 = make_float2(acc[mt][nt][2] + bi1, acc[mt][nt][3] + bi1);
                            *reinterpret_cast<float2*>(o) = v0;
                            *reinterpret_cast<float2*>(o + (size_t)8 * OW * OW) = v1;
                        }
                        #pragma unroll
                        for (int i = 0; i < 4; i++) acc[mt][nt][i] = 0.f;
                    }
                }
            }
        }
    } else {
        // ======================= PRODUCERS =======================
        const int pw   = warp - 8;       // 0..7
        const int ptid = tid - 256;      // 0..255
        const int ic0  = pw * 8;

        for (int s = 0; s < NSTAGE; s++) {
            const int buf  = s & 1;
            const int tile = s / 3;
            const int ky   = s - 3 * tile;

            if (s >= 2) BAR_SYNC(3 + buf);           // wait EMPTY

            // ---- W image for (b, ky): flat cp.async (24 KB) ----
            {
                const char* src = reinterpret_cast<const char*>(&g_wm[b][ky][0][0][0]);
                const uint32_t dst = sb + SM_W + (uint32_t)buf * WIMG;
                #pragma unroll
                for (int i = 0; i < 6; i++) {
                    uint32_t e = ((uint32_t)ptid + (uint32_t)i * 256u) * 16u;
                    cp_async16(dst + e, src + e);
                }
                cp_commit();
            }

            // ---- x row y = oy0 + tile + ky: LDG -> hi/lo cvt -> STS ----
            {
                const int y = oy0 + tile + ky;       // <= 127
                const float* xr = x + ((size_t)b * INC * HW + (size_t)y) * HW;
                const uint32_t xbase = SM_X + (uint32_t)buf * XBUF;
                #pragma unroll
                for (int k = 0; k < 4; k++) {
                    int c = k * 32 + L;              // 0..127
                    float v[8];
                    #pragma unroll
                    for (int i = 0; i < 8; i++)
                        v[i] = __ldg(xr + (size_t)(ic0 + i) * HW * HW + c);
                    uint32_t hi[4], lo[4];
                    #pragma unroll
                    for (int i = 0; i < 4; i++) {
                        __half h0 = __float2half_rn(v[2 * i]);
                        __half h1 = __float2half_rn(v[2 * i + 1]);
                        __half l0 = __float2half_rn(v[2 * i]     - __half2float(h0));
                        __half l1 = __float2half_rn(v[2 * i + 1] - __half2float(h1));
                        hi[i] = pack_h2(h0, h1);
                        lo[i] = pack_h2(l0, l1);
                    }
                    uint32_t p   = (uint32_t)(pw ^ (c & 7));
                    uint32_t off = xbase + (uint32_t)c * 128u + p * 16u;
                    *reinterpret_cast<uint4*>(smem + off)         = make_uint4(hi[0], hi[1], hi[2], hi[3]);
                    *reinterpret_cast<uint4*>(smem + off + XPART) = make_uint4(lo[0], lo[1], lo[2], lo[3]);
                }
            }

            cp_wait0();                              // W copies landed
            BAR_ARRIVE(1 + buf);                     // signal FULL
        }
    }
}

// ============================================================
extern "C" void kernel_launch(void* const* d_in, const int* in_sizes, int n_in,
                              void* d_out, int out_size)
{
    const float* x     = (const float*)d_in[0];
    const float* fc_in = (const float*)d_in[1];
    const float* w1    = (const float*)d_in[2];
    const float* b1    = (const float*)d_in[3];
    const float* w2    = (const float*)d_in[4];
    const float* b2    = (const float*)d_in[5];
    const float* w3    = (const float*)d_in[6];
    const float* b3    = (const float*)d_in[7];
    float* out = (float*)d_out;

    cudaFuncSetAttribute(conv_mma, cudaFuncAttributeMaxDynamicSharedMemorySize, SM_TOTAL);

    gemv1_kernel<<<dim3(FC / 8, NB), 256>>>(fc_in, w1, b1);
    gemv2_kernel<<<dim3(FC / 8, NB), 256>>>(w2, b2);
    wbgen_kernel<<<dim3(GROUPS, (OPG + 255) / 256), 256>>>(w3, b3);
    conv_mma<<<NB * CTA_PER_B, 512, SM_TOTAL>>>(x, out);
}

// round 14
// speedup vs baseline: 1.4334x; 1.0510x over previous
#include <cuda_runtime.h>
#include <cuda_fp16.h>
#include <cstdint>

// ---------------- problem constants ----------------
#define NB      16
#define INC     64
#define OUTC    64
#define HW      128
#define OW      126
#define FC      512
#define GROUPS  4
#define OPG     9232
#define IPG     128
#define CNNP    36928
#define NWCOL   36864

// ---------------- scratch (device-code refs only) ----------------
__device__ float g_h1[NB * FC];
__device__ float g_h2[NB * FC];
// single-fp16 weights, pre-swizzled: [b][ky][kx][oc][ic(swizzled units)]
__device__ __half g_wm[NB][3][3][64][64];
__device__ float g_bias[NB * OUTC];

// smem layout (dynamic): resident all-ky W + 4-slot x-row ring
#define WIMG      24576                    // one ky image
#define SM_W      0                        // 3 * 24576 = 73728
#define SM_X      73728                    // 4 slots x 32768
#define XSLOT     32768
#define XPART     16384
#define SM_BIAS   204800                   // 256 B
#define SM_TOTAL  205056

#define TILES_PER_CTA 7
#define CTA_PER_B     18                   // 18 * 7 = 126 rows
#define NROWS         (TILES_PER_CTA + 2)  // 9 distinct x rows per CTA

// named barriers (512 threads): FULL[slot]=1+slot, EMPTY[slot]=5+slot
#define BAR_SYNC(id)   asm volatile("bar.sync %0, 512;"   :: "r"(id) : "memory")
#define BAR_ARRIVE(id) asm volatile("bar.arrive %0, 512;" :: "r"(id) : "memory")

// ---------------- PTX helpers ----------------
__device__ __forceinline__ unsigned int smem_u32(const void* p) {
    unsigned int a;
    asm("{ .reg .u64 t; cvta.to.shared.u64 t, %1; cvt.u32.u64 %0, t; }"
        : "=r"(a) : "l"(p));
    return a;
}
__device__ __forceinline__ void cp_async16(unsigned int sdst, const void* gsrc) {
    asm volatile("cp.async.cg.shared.global [%0], [%1], 16;" :: "r"(sdst), "l"(gsrc));
}
__device__ __forceinline__ void cp_commit() { asm volatile("cp.async.commit_group;"); }
__device__ __forceinline__ void cp_wait0()  { asm volatile("cp.async.wait_group 0;"); }

__device__ __forceinline__ void ldsm_x4(uint32_t& r0, uint32_t& r1, uint32_t& r2,
                                        uint32_t& r3, uint32_t addr) {
    asm volatile("ldmatrix.sync.aligned.m8n8.x4.shared.b16 {%0,%1,%2,%3}, [%4];"
                 : "=r"(r0), "=r"(r1), "=r"(r2), "=r"(r3) : "r"(addr));
}
__device__ __forceinline__ void mma16816(float* c, const uint32_t* a,
                                         uint32_t b0, uint32_t b1) {
    asm volatile(
        "mma.sync.aligned.m16n8k16.row.col.f32.f16.f16.f32 "
        "{%0,%1,%2,%3}, {%4,%5,%6,%7}, {%8,%9}, {%0,%1,%2,%3};"
        : "+f"(c[0]), "+f"(c[1]), "+f"(c[2]), "+f"(c[3])
        : "r"(a[0]), "r"(a[1]), "r"(a[2]), "r"(a[3]), "r"(b0), "r"(b1));
}
__device__ __forceinline__ uint32_t pack_h2(__half a, __half b) {
    return (uint32_t)__half_as_ushort(a) | ((uint32_t)__half_as_ushort(b) << 16);
}

// ============================================================
// Kernel 1: GEMV + bias + relu, warp-per-output.
// ============================================================
__device__ __forceinline__ void gemv_body(
    const float* __restrict__ in, const float* __restrict__ W,
    const float* __restrict__ bias, float* __restrict__ out)
{
    const int lane = threadIdx.x & 31;
    const int warp = threadIdx.x >> 5;
    const int b = blockIdx.y;
    const int t = blockIdx.x * 8 + warp;

    const float4* in4 = reinterpret_cast<const float4*>(in + (size_t)b * FC);
    const float4* w4  = reinterpret_cast<const float4*>(W + (size_t)t * FC);

    float s = 0.f;
    #pragma unroll
    for (int i = 0; i < 4; i++) {
        float4 a = in4[lane + 32 * i];
        float4 w = w4[lane + 32 * i];
        s += a.x * w.x + a.y * w.y + a.z * w.z + a.w * w.w;
    }
    #pragma unroll
    for (int off = 16; off > 0; off >>= 1)
        s += __shfl_xor_sync(0xffffffffu, s, off);
    if (lane == 0)
        out[(size_t)b * FC + t] = fmaxf(s + bias[t], 0.f);
}
__global__ __launch_bounds__(256) void gemv1_kernel(
    const float* __restrict__ fc_in, const float* __restrict__ w1,
    const float* __restrict__ b1) { gemv_body(fc_in, w1, b1, g_h1); }
__global__ __launch_bounds__(256) void gemv2_kernel(
    const float* __restrict__ w2, const float* __restrict__ b2) { gemv_body(g_h1, w2, b2, g_h2); }

// ============================================================
// Kernel 2: wbgen -> single-fp16, unit-swizzled weight images + bias.
// ============================================================
__global__ __launch_bounds__(256) void wbgen_kernel(
    const float* __restrict__ w3, const float* __restrict__ b3)
{
    __shared__ __align__(16) float4 s_h2[NB][IPG / 4];
    int g = blockIdx.x;
    int j = blockIdx.y * 256 + threadIdx.x;

    for (int e = threadIdx.x; e < NB * IPG / 4; e += 256) {
        int bb = e >> 5, k = e & 31;
        s_h2[bb][k] = reinterpret_cast<const float4*>(g_h2 + bb * FC + g * IPG)[k];
    }
    __syncthreads();
    if (j >= OPG) return;

    float acc[NB];
    #pragma unroll
    for (int bb = 0; bb < NB; bb++) acc[bb] = 0.f;

    const float4* wr = reinterpret_cast<const float4*>(w3 + ((size_t)g * OPG + j) * IPG);
    #pragma unroll 4
    for (int k = 0; k < IPG / 4; k++) {
        float4 w = wr[k];
        #pragma unroll
        for (int bb = 0; bb < NB; bb++) {
            float4 h = s_h2[bb][k];
            acc[bb] += w.x * h.x + w.y * h.y + w.z * h.z + w.w * h.w;
        }
    }
    float bias = b3[g * OPG + j];
    int col = g * OPG + j;

    if (col < NWCOL) {
        // col = oc*576 + ic*9 + ky*3 + kx
        int oc = col / 576;
        int r  = col - oc * 576;
        int ic = r / 9;
        int kt = r - ic * 9;
        int ky = kt / 3;
        int kx = kt - ky * 3;
        int ic_sw = (((ic >> 3) ^ (oc & 7)) << 3) | (ic & 7);
        #pragma unroll
        for (int bb = 0; bb < NB; bb++) {
            float w = fmaxf(acc[bb] + bias, 0.f);
            g_wm[bb][ky][kx][oc][ic_sw] = __float2half_rn(w);
        }
    } else {
        int oc = col - NWCOL;
        #pragma unroll
        for (int bb = 0; bb < NB; bb++)
            g_bias[bb * OUTC + oc] = fmaxf(acc[bb] + bias, 0.f);
    }
}

// ============================================================
// Kernel 3: warp-specialized HMMA conv; resident W + x-row ring.
// 512 thr: warps 0-7 consumers, 8-15 producers. CTA = 7 rows of one b.
// W (all 3 ky, 72KB) staged once; 9 distinct x rows staged once each
// into a 4-slot ring. Per-slot named-barrier FULL/EMPTY protocol.
// ============================================================
__global__ __launch_bounds__(512, 1) void conv_mma(
    const float* __restrict__ x, float* __restrict__ out)
{
    extern __shared__ char smem[];
    const uint32_t sb = smem_u32(smem);
    const int tid  = threadIdx.x;
    const int warp = tid >> 5;
    const int L    = tid & 31;

    const int b   = blockIdx.x / CTA_PER_B;
    const int oy0 = (blockIdx.x - b * CTA_PER_B) * TILES_PER_CTA;

    float* s_bias = reinterpret_cast<float*>(smem + SM_BIAS);
    if (tid < OUTC) s_bias[tid] = g_bias[b * OUTC + tid];

    if (warp < 8) {
        // ======================= CONSUMERS =======================
        const int gq  = L >> 3;
        const int gi  = L & 7;
        const int ocw = (warp & 1) * 32;
        const int pxw = (warp >> 1) * 32;

        float acc[2][4][4];
        #pragma unroll
        for (int mt = 0; mt < 2; mt++)
            #pragma unroll
            for (int nt = 0; nt < 4; nt++)
                #pragma unroll
                for (int i = 0; i < 4; i++) acc[mt][nt][i] = 0.f;

        // wait W + first three rows
        BAR_SYNC(1 + 0);
        BAR_SYNC(1 + 1);
        BAR_SYNC(1 + 2);

        for (int t = 0; t < TILES_PER_CTA; t++) {
            if (t >= 1) BAR_SYNC(1 + ((t + 2) & 3));   // newly needed row

            for (int ky = 0; ky < 3; ky++) {
                const uint32_t wb_ = sb + SM_W + (uint32_t)ky * WIMG;
                const uint32_t xb_ = sb + SM_X + (uint32_t)((t + ky) & 3) * XSLOT;
                for (int kx = 0; kx < 3; kx++) {
                    #pragma unroll
                    for (int ks = 0; ks < 4; ks++) {
                        const int ub = ks * 2;
                        uint32_t a[2][4];
                        #pragma unroll
                        for (int mt = 0; mt < 2; mt++) {
                            int row = ocw + mt * 16 + (gq & 1) * 8 + gi;
                            int u   = ub + (gq >> 1);
                            uint32_t addr = wb_ +
                                (uint32_t)((kx * 64 + row) * 128 +
                                           ((u ^ (row & 7)) * 16));
                            ldsm_x4(a[mt][0], a[mt][1], a[mt][2], a[mt][3], addr);
                        }
                        uint32_t bb[2][2][4];
                        #pragma unroll
                        for (int part = 0; part < 2; part++) {
                            #pragma unroll
                            for (int np = 0; np < 2; np++) {
                                int c = pxw + np * 16 + kx + (gq >> 1) * 8 + gi;
                                if (c > 127) c = 127;   // feeds only discarded px
                                uint32_t addr = xb_ + (uint32_t)part * XPART +
                                    (uint32_t)(c * 128 +
                                               (((ub + (gq & 1)) ^ (c & 7)) * 16));
                                ldsm_x4(bb[part][np][0], bb[part][np][1],
                                        bb[part][np][2], bb[part][np][3], addr);
                            }
                        }
                        #pragma unroll
                        for (int mt = 0; mt < 2; mt++) {
                            #pragma unroll
                            for (int nt = 0; nt < 4; nt++) {
                                int np = nt >> 1, q2 = (nt & 1) * 2;
                                mma16816(acc[mt][nt], a[mt], bb[0][np][q2], bb[0][np][q2 + 1]);
                                mma16816(acc[mt][nt], a[mt], bb[1][np][q2], bb[1][np][q2 + 1]);
                            }
                        }
                    }
                }
            }

            BAR_ARRIVE(5 + (t & 3));                   // row t's slot now free

            // ---- epilogue for this tile ----
            {
                const int oy = oy0 + t;
                const int r4 = L >> 2;
                const int q  = (L & 3) * 2;
                #pragma unroll
                for (int mt = 0; mt < 2; mt++) {
                    int oc = ocw + mt * 16 + r4;
                    float bi0 = s_bias[oc];
                    float bi1 = s_bias[oc + 8];
                    #pragma unroll
                    for (int nt = 0; nt < 4; nt++) {
                        int px = pxw + nt * 8 + q;
                        if (px < OW) {
                            float* o = out + (((size_t)(b * OUTC + oc)) * OW + oy) * OW + px;
                            float2 v0 = make_float2(acc[mt][nt][0] + bi0, acc[mt][nt][1] + bi0);
                            float2 v1 = make_float2(acc[mt][nt][2] + bi1, acc[mt][nt][3] + bi1);
                            *reinterpret_cast<float2*>(o) = v0;
                            *reinterpret_cast<float2*>(o + (size_t)8 * OW * OW) = v1;
                        }
                        #pragma unroll
                        for (int i = 0; i < 4; i++) acc[mt][nt][i] = 0.f;
                    }
                }
            }
        }
    } else {
        // ======================= PRODUCERS =======================
        const int pw   = warp - 8;       // 0..7
        const int ptid = tid - 256;      // 0..255
        const int ic0  = pw * 8;

        // stage one x row j (y = oy0 + j) into ring slot j&3
        auto stage_row = [&](int j) {
            const int y = oy0 + j;                     // <= 127
            const float* xr = x + ((size_t)b * INC * HW + (size_t)y) * HW;
            const uint32_t xbase = SM_X + (uint32_t)(j & 3) * XSLOT;
            #pragma unroll
            for (int k = 0; k < 4; k++) {
                int c = k * 32 + L;                    // 0..127
                float v[8];
                #pragma unroll
                for (int i = 0; i < 8; i++)
                    v[i] = __ldg(xr + (size_t)(ic0 + i) * HW * HW + c);
                uint32_t hi[4], lo[4];
                #pragma unroll
                for (int i = 0; i < 4; i++) {
                    __half h0 = __float2half_rn(v[2 * i]);
                    __half h1 = __float2half_rn(v[2 * i + 1]);
                    __half l0 = __float2half_rn(v[2 * i]     - __half2float(h0));
                    __half l1 = __float2half_rn(v[2 * i + 1] - __half2float(h1));
                    hi[i] = pack_h2(h0, h1);
                    lo[i] = pack_h2(l0, l1);
                }
                uint32_t p   = (uint32_t)(pw ^ (c & 7));
                uint32_t off = xbase + (uint32_t)c * 128u + p * 16u;
                *reinterpret_cast<uint4*>(smem + off)         = make_uint4(hi[0], hi[1], hi[2], hi[3]);
                *reinterpret_cast<uint4*>(smem + off + XPART) = make_uint4(lo[0], lo[1], lo[2], lo[3]);
            }
        };

        // ---- W: all 3 ky images, staged once (72 KB) ----
        {
            const char* src = reinterpret_cast<const char*>(&g_wm[b][0][0][0][0]);
            #pragma unroll
            for (int i = 0; i < 18; i++) {
                uint32_t e = ((uint32_t)ptid + (uint32_t)i * 256u) * 16u;
                cp_async16(sb + SM_W + e, src + e);
            }
            cp_commit();
        }

        stage_row(0);
        cp_wait0();                                    // W landed
        BAR_ARRIVE(1 + 0);
        stage_row(1);
        BAR_ARRIVE(1 + 1);
        stage_row(2);
        BAR_ARRIVE(1 + 2);

        for (int j = 3; j < NROWS; j++) {
            if (j >= 4) BAR_SYNC(5 + (j & 3));         // wait slot free
            stage_row(j);
            BAR_ARRIVE(1 + (j & 3));
        }
        // drain remaining EMPTY arrivals so barrier counts balance
        for (int t = NROWS - 4; t < TILES_PER_CTA; t++)
            BAR_SYNC(5 + (t & 3));
    }
}

// ============================================================
extern "C" void kernel_launch(void* const* d_in, const int* in_sizes, int n_in,
                              void* d_out, int out_size)
{
    const float* x     = (const float*)d_in[0];
    const float* fc_in = (const float*)d_in[1];
    const float* w1    = (const float*)d_in[2];
    const float* b1    = (const float*)d_in[3];
    const float* w2    = (const float*)d_in[4];
    const float* b2    = (const float*)d_in[5];
    const float* w3    = (const float*)d_in[6];
    const float* b3    = (const float*)d_in[7];
    float* out = (float*)d_out;

    cudaFuncSetAttribute(conv_mma, cudaFuncAttributeMaxDynamicSharedMemorySize, SM_TOTAL);

    gemv1_kernel<<<dim3(FC / 8, NB), 256>>>(fc_in, w1, b1);
    gemv2_kernel<<<dim3(FC / 8, NB), 256>>>(w2, b2);
    wbgen_kernel<<<dim3(GROUPS, (OPG + 255) / 256), 256>>>(w3, b3);
    conv_mma<<<NB * CTA_PER_B, 512, SM_TOTAL>>>(x, out);
}

// round 15
// speedup vs baseline: 2.0607x; 1.4377x over previous
#include <cuda_runtime.h>
#include <cuda_fp16.h>
#include <cstdint>

// ---------------- problem constants ----------------
#define NB      16
#define INC     64
#define OUTC    64
#define HW      128
#define OW      126
#define FC      512
#define GROUPS  4
#define OPG     9232
#define IPG     128
#define CNNP    36928
#define NWCOL   36864

// ---------------- scratch (device-code refs only) ----------------
__device__ float g_h1[NB * FC];
__device__ float g_h2[NB * FC];
// single-fp16 weights, pre-swizzled: [b][ky][kx][oc][ic(swizzled units)]
__device__ __half g_wm[NB][3][3][64][64];
__device__ float g_bias[NB * OUTC];

// smem layout (dynamic): resident all-ky W + 6-slot x-row ring (fp16 only)
#define WIMG      24576                    // one ky image
#define SM_W      0                        // 3 * 24576 = 73728
#define SM_X      73728                    // 6 slots x 16384
#define XSLOT     16384
#define SM_BIAS   172032                   // 256 B
#define SM_TOTAL  172288

#define PAIRS_PER_CTA 7                    // 7 pairs = 14 rows
#define CTA_PER_B     9                    // 9 * 14 = 126 rows -> 144 CTAs (1 wave)
#define NROWS         16                   // distinct x rows per CTA (0..15)

// named barriers (512 threads): FULL[slot]=1+slot (1..6), EMPTY[slot]=7+slot (7..12)
#define BAR_SYNC(id)   asm volatile("bar.sync %0, 512;"   :: "r"(id) : "memory")
#define BAR_ARRIVE(id) asm volatile("bar.arrive %0, 512;" :: "r"(id) : "memory")

// ---------------- PTX helpers ----------------
__device__ __forceinline__ unsigned int smem_u32(const void* p) {
    unsigned int a;
    asm("{ .reg .u64 t; cvta.to.shared.u64 t, %1; cvt.u32.u64 %0, t; }"
        : "=r"(a) : "l"(p));
    return a;
}
__device__ __forceinline__ void cp_async16(unsigned int sdst, const void* gsrc) {
    asm volatile("cp.async.cg.shared.global [%0], [%1], 16;" :: "r"(sdst), "l"(gsrc));
}
__device__ __forceinline__ void cp_commit() { asm volatile("cp.async.commit_group;"); }
__device__ __forceinline__ void cp_wait0()  { asm volatile("cp.async.wait_group 0;"); }

__device__ __forceinline__ void ldsm_x4(uint32_t& r0, uint32_t& r1, uint32_t& r2,
                                        uint32_t& r3, uint32_t addr) {
    asm volatile("ldmatrix.sync.aligned.m8n8.x4.shared.b16 {%0,%1,%2,%3}, [%4];"
                 : "=r"(r0), "=r"(r1), "=r"(r2), "=r"(r3) : "r"(addr));
}
__device__ __forceinline__ void mma16816(float* c, const uint32_t* a,
                                         uint32_t b0, uint32_t b1) {
    asm volatile(
        "mma.sync.aligned.m16n8k16.row.col.f32.f16.f16.f32 "
        "{%0,%1,%2,%3}, {%4,%5,%6,%7}, {%8,%9}, {%0,%1,%2,%3};"
        : "+f"(c[0]), "+f"(c[1]), "+f"(c[2]), "+f"(c[3])
        : "r"(a[0]), "r"(a[1]), "r"(a[2]), "r"(a[3]), "r"(b0), "r"(b1));
}
__device__ __forceinline__ uint32_t pack_h2(__half a, __half b) {
    return (uint32_t)__half_as_ushort(a) | ((uint32_t)__half_as_ushort(b) << 16);
}

// ============================================================
// Kernel 1: GEMV + bias + relu, warp-per-output.
// ============================================================
__device__ __forceinline__ void gemv_body(
    const float* __restrict__ in, const float* __restrict__ W,
    const float* __restrict__ bias, float* __restrict__ out)
{
    const int lane = threadIdx.x & 31;
    const int warp = threadIdx.x >> 5;
    const int b = blockIdx.y;
    const int t = blockIdx.x * 8 + warp;

    const float4* in4 = reinterpret_cast<const float4*>(in + (size_t)b * FC);
    const float4* w4  = reinterpret_cast<const float4*>(W + (size_t)t * FC);

    float s = 0.f;
    #pragma unroll
    for (int i = 0; i < 4; i++) {
        float4 a = in4[lane + 32 * i];
        float4 w = w4[lane + 32 * i];
        s += a.x * w.x + a.y * w.y + a.z * w.z + a.w * w.w;
    }
    #pragma unroll
    for (int off = 16; off > 0; off >>= 1)
        s += __shfl_xor_sync(0xffffffffu, s, off);
    if (lane == 0)
        out[(size_t)b * FC + t] = fmaxf(s + bias[t], 0.f);
}
__global__ __launch_bounds__(256) void gemv1_kernel(
    const float* __restrict__ fc_in, const float* __restrict__ w1,
    const float* __restrict__ b1) { gemv_body(fc_in, w1, b1, g_h1); }
__global__ __launch_bounds__(256) void gemv2_kernel(
    const float* __restrict__ w2, const float* __restrict__ b2) { gemv_body(g_h1, w2, b2, g_h2); }

// ============================================================
// Kernel 2: wbgen -> single-fp16, unit-swizzled weight images + bias.
// ============================================================
__global__ __launch_bounds__(256) void wbgen_kernel(
    const float* __restrict__ w3, const float* __restrict__ b3)
{
    __shared__ __align__(16) float4 s_h2[NB][IPG / 4];
    int g = blockIdx.x;
    int j = blockIdx.y * 256 + threadIdx.x;

    for (int e = threadIdx.x; e < NB * IPG / 4; e += 256) {
        int bb = e >> 5, k = e & 31;
        s_h2[bb][k] = reinterpret_cast<const float4*>(g_h2 + bb * FC + g * IPG)[k];
    }
    __syncthreads();
    if (j >= OPG) return;

    float acc[NB];
    #pragma unroll
    for (int bb = 0; bb < NB; bb++) acc[bb] = 0.f;

    const float4* wr = reinterpret_cast<const float4*>(w3 + ((size_t)g * OPG + j) * IPG);
    #pragma unroll 4
    for (int k = 0; k < IPG / 4; k++) {
        float4 w = wr[k];
        #pragma unroll
        for (int bb = 0; bb < NB; bb++) {
            float4 h = s_h2[bb][k];
            acc[bb] += w.x * h.x + w.y * h.y + w.z * h.z + w.w * h.w;
        }
    }
    float bias = b3[g * OPG + j];
    int col = g * OPG + j;

    if (col < NWCOL) {
        // col = oc*576 + ic*9 + ky*3 + kx
        int oc = col / 576;
        int r  = col - oc * 576;
        int ic = r / 9;
        int kt = r - ic * 9;
        int ky = kt / 3;
        int kx = kt - ky * 3;
        int ic_sw = (((ic >> 3) ^ (oc & 7)) << 3) | (ic & 7);
        #pragma unroll
        for (int bb = 0; bb < NB; bb++) {
            float w = fmaxf(acc[bb] + bias, 0.f);
            g_wm[bb][ky][kx][oc][ic_sw] = __float2half_rn(w);
        }
    } else {
        int oc = col - NWCOL;
        #pragma unroll
        for (int bb = 0; bb < NB; bb++)
            g_bias[bb * OUTC + oc] = fmaxf(acc[bb] + bias, 0.f);
    }
}

// ============================================================
// Kernel 3: warp-specialized HMMA conv, pure fp16 x fp16 (1 MMA/product),
// 2-row output tiles (A-fragment reuse). 512 thr: warps 0-7 consumers,
// 8-15 producers. CTA = 14 rows (7 pairs) of one sample; resident W,
// 6-slot fp16 x-row ring, per-slot named-barrier FULL/EMPTY.
// ============================================================
__global__ __launch_bounds__(512, 1) void conv_mma(
    const float* __restrict__ x, float* __restrict__ out)
{
    extern __shared__ char smem[];
    const uint32_t sb = smem_u32(smem);
    const int tid  = threadIdx.x;
    const int warp = tid >> 5;
    const int L    = tid & 31;

    const int b   = blockIdx.x / CTA_PER_B;
    const int oy0 = (blockIdx.x - b * CTA_PER_B) * (2 * PAIRS_PER_CTA);

    float* s_bias = reinterpret_cast<float*>(smem + SM_BIAS);
    if (tid < OUTC) s_bias[tid] = g_bias[b * OUTC + tid];

    if (warp < 8) {
        // ======================= CONSUMERS =======================
        const int gq  = L >> 3;
        const int gi  = L & 7;
        const int ocw = (warp & 1) * 32;
        const int pxw = (warp >> 1) * 32;

        float acc[2][2][4][4];   // [row][mt][nt][4]
        #pragma unroll
        for (int r = 0; r < 2; r++)
            #pragma unroll
            for (int mt = 0; mt < 2; mt++)
                #pragma unroll
                for (int nt = 0; nt < 4; nt++)
                    #pragma unroll
                    for (int i = 0; i < 4; i++) acc[r][mt][nt][i] = 0.f;

        // rows 0..3 needed for pair 0 (also implies W landed)
        BAR_SYNC(1 + 0); BAR_SYNC(1 + 1); BAR_SYNC(1 + 2); BAR_SYNC(1 + 3);

        for (int p = 0; p < PAIRS_PER_CTA; p++) {
            if (p >= 1) {
                BAR_SYNC(1 + (2 * p + 2) % 6);   // newly needed rows
                BAR_SYNC(1 + (2 * p + 3) % 6);
            }

            for (int ky = 0; ky < 3; ky++) {
                const uint32_t wb_ = sb + SM_W + (uint32_t)ky * WIMG;
                const uint32_t xr0 = sb + SM_X + (uint32_t)((2 * p + ky) % 6) * XSLOT;
                const uint32_t xr1 = sb + SM_X + (uint32_t)((2 * p + ky + 1) % 6) * XSLOT;
                for (int kx = 0; kx < 3; kx++) {
                    #pragma unroll
                    for (int ks = 0; ks < 4; ks++) {
                        const int ub = ks * 2;
                        // A fragments (weights), reused for both rows
                        uint32_t a[2][4];
                        #pragma unroll
                        for (int mt = 0; mt < 2; mt++) {
                            int row = ocw + mt * 16 + (gq & 1) * 8 + gi;
                            int u   = ub + (gq >> 1);
                            uint32_t addr = wb_ +
                                (uint32_t)((kx * 64 + row) * 128 +
                                           ((u ^ (row & 7)) * 16));
                            ldsm_x4(a[mt][0], a[mt][1], a[mt][2], a[mt][3], addr);
                        }
                        int c = pxw + kx + (gq >> 1) * 8 + gi;   // + np*16 below
                        #pragma unroll
                        for (int r = 0; r < 2; r++) {
                            const uint32_t xb_ = r ? xr1 : xr0;
                            uint32_t bb[2][4];
                            #pragma unroll
                            for (int np = 0; np < 2; np++) {
                                int cc = c + np * 16;
                                if (cc > 127) cc = 127;  // feeds only discarded px
                                uint32_t addr = xb_ +
                                    (uint32_t)(cc * 128 +
                                               (((ub + (gq & 1)) ^ (cc & 7)) * 16));
                                ldsm_x4(bb[np][0], bb[np][1], bb[np][2], bb[np][3], addr);
                            }
                            #pragma unroll
                            for (int mt = 0; mt < 2; mt++) {
                                #pragma unroll
                                for (int nt = 0; nt < 4; nt++) {
                                    int np = nt >> 1, q2 = (nt & 1) * 2;
                                    mma16816(acc[r][mt][nt], a[mt],
                                             bb[np][q2], bb[np][q2 + 1]);
                                }
                            }
                        }
                    }
                }
            }

            BAR_ARRIVE(7 + (2 * p) % 6);         // release both rows
            BAR_ARRIVE(7 + (2 * p + 1) % 6);

            // ---- epilogue: rows 2p, 2p+1 ----
            {
                const int r4 = L >> 2;
                const int q  = (L & 3) * 2;
                #pragma unroll
                for (int r = 0; r < 2; r++) {
                    const int oy = oy0 + 2 * p + r;
                    #pragma unroll
                    for (int mt = 0; mt < 2; mt++) {
                        int oc = ocw + mt * 16 + r4;
                        float bi0 = s_bias[oc];
                        float bi1 = s_bias[oc + 8];
                        #pragma unroll
                        for (int nt = 0; nt < 4; nt++) {
                            int px = pxw + nt * 8 + q;
                            if (px < OW) {
                                float* o = out + (((size_t)(b * OUTC + oc)) * OW + oy) * OW + px;
                                float2 v0 = make_float2(acc[r][mt][nt][0] + bi0,
                                                        acc[r][mt][nt][1] + bi0);
                                float2 v1 = make_float2(acc[r][mt][nt][2] + bi1,
                                                        acc[r][mt][nt][3] + bi1);
                                *reinterpret_cast<float2*>(o) = v0;
                                *reinterpret_cast<float2*>(o + (size_t)8 * OW * OW) = v1;
                            }
                            #pragma unroll
                            for (int i = 0; i < 4; i++) acc[r][mt][nt][i] = 0.f;
                        }
                    }
                }
            }
        }
    } else {
        // ======================= PRODUCERS =======================
        const int pw   = warp - 8;       // 0..7
        const int ptid = tid - 256;      // 0..255
        const int ic0  = pw * 8;

        // stage one x row j (y = oy0 + j, fp16 only) into ring slot j%6
        auto stage_row = [&](int j) {
            const int y = oy0 + j;                     // <= 127
            const float* xr = x + ((size_t)b * INC * HW + (size_t)y) * HW;
            const uint32_t xbase = SM_X + (uint32_t)(j % 6) * XSLOT;
            #pragma unroll
            for (int k = 0; k < 4; k++) {
                int c = k * 32 + L;                    // 0..127
                float v[8];
                #pragma unroll
                for (int i = 0; i < 8; i++)
                    v[i] = __ldg(xr + (size_t)(ic0 + i) * HW * HW + c);
                uint32_t hi[4];
                #pragma unroll
                for (int i = 0; i < 4; i++)
                    hi[i] = pack_h2(__float2half_rn(v[2 * i]),
                                    __float2half_rn(v[2 * i + 1]));
                uint32_t pu  = (uint32_t)(pw ^ (c & 7));
                uint32_t off = xbase + (uint32_t)c * 128u + pu * 16u;
                *reinterpret_cast<uint4*>(smem + off) = make_uint4(hi[0], hi[1], hi[2], hi[3]);
            }
        };

        // ---- W: all 3 ky images, staged once (72 KB) ----
        {
            const char* src = reinterpret_cast<const char*>(&g_wm[b][0][0][0][0]);
            #pragma unroll
            for (int i = 0; i < 18; i++) {
                uint32_t e = ((uint32_t)ptid + (uint32_t)i * 256u) * 16u;
                cp_async16(sb + SM_W + e, src + e);
            }
            cp_commit();
        }

        stage_row(0);
        cp_wait0();                                    // W landed
        BAR_ARRIVE(1 + 0);
        #pragma unroll
        for (int j = 1; j < 6; j++) {
            stage_row(j);
            BAR_ARRIVE(1 + j);
        }
        for (int j = 6; j < NROWS; j++) {
            BAR_SYNC(7 + (j % 6));                     // wait slot free
            stage_row(j);
            BAR_ARRIVE(1 + (j % 6));
        }
        // drain leftover EMPTY arrivals (rows 10..13 -> slots 4,5,0,1)
        BAR_SYNC(7 + 4); BAR_SYNC(7 + 5); BAR_SYNC(7 + 0); BAR_SYNC(7 + 1);
    }
}

// ============================================================
extern "C" void kernel_launch(void* const* d_in, const int* in_sizes, int n_in,
                              void* d_out, int out_size)
{
    const float* x     = (const float*)d_in[0];
    const float* fc_in = (const float*)d_in[1];
    const float* w1    = (const float*)d_in[2];
    const float* b1    = (const float*)d_in[3];
    const float* w2    = (const float*)d_in[4];
    const float* b2    = (const float*)d_in[5];
    const float* w3    = (const float*)d_in[6];
    const float* b3    = (const float*)d_in[7];
    float* out = (float*)d_out;

    cudaFuncSetAttribute(conv_mma, cudaFuncAttributeMaxDynamicSharedMemorySize, SM_TOTAL);

    gemv1_kernel<<<dim3(FC / 8, NB), 256>>>(fc_in, w1, b1);
    gemv2_kernel<<<dim3(FC / 8, NB), 256>>>(w2, b2);
    wbgen_kernel<<<dim3(GROUPS, (OPG + 255) / 256), 256>>>(w3, b3);
    conv_mma<<<NB * CTA_PER_B, 512, SM_TOTAL>>>(x, out);
}